// round 2
// baseline (speedup 1.0000x reference)
#include <cuda_runtime.h>
#include <math.h>

#define B_ROWS 16384
#define NCLS   1000
#define KDIM   1000
#define EPS    0.1f

#define BM 128
#define BN 128
#define BK 8
#define TM 8
#define TN 8
#define LDS_STRIDE 132   // 128 + 4 pad to kill store bank conflicts

// Scratch (allocation-free rule: __device__ globals)
__device__ float g_S[(size_t)B_ROWS * NCLS];   // logits S[b,n] = 2*dot - csum[n]
__device__ float g_csum[NCLS];
__device__ float g_row[B_ROWS];
__device__ int   g_labmode;                    // 1 = int32 labels, 0 = int64 labels

// ---------------------------------------------------------------------------
// Detect label dtype: if labels are int64 (little-endian), every odd int32
// word is the hi word of a value in [0,1000) -> all zero. If int32, the odd
// words are actual labels; 8192 of them all being zero has ~nil probability.
// Only scans the first 16384 int32s, which is in-bounds for either dtype.
// ---------------------------------------------------------------------------
__global__ void detect_kernel(const int* __restrict__ l32) {
    __shared__ int s_any;
    if (threadIdx.x == 0) s_any = 0;
    __syncthreads();
    int local = 0;
    for (int i = threadIdx.x; i < B_ROWS / 2; i += blockDim.x)
        local |= l32[2 * i + 1];
    if (local) atomicOr(&s_any, 1);
    __syncthreads();
    if (threadIdx.x == 0) g_labmode = (s_any != 0) ? 1 : 0;
}

// ---------------------------------------------------------------------------
// csum[n] = sum_d code_book[n, d]   (one warp per codebook row)
// ---------------------------------------------------------------------------
__global__ void csum_kernel(const float* __restrict__ Cb) {
    int warp = (blockIdx.x * blockDim.x + threadIdx.x) >> 5;
    int lane = threadIdx.x & 31;
    if (warp >= NCLS) return;
    const float* r = Cb + (size_t)warp * KDIM;
    float s = 0.f;
    for (int i = lane; i < KDIM; i += 32) s += r[i];
    #pragma unroll
    for (int off = 16; off > 0; off >>= 1)
        s += __shfl_xor_sync(0xFFFFFFFFu, s, off);
    if (lane == 0) g_csum[warp] = s;
}

// ---------------------------------------------------------------------------
// Tiled SGEMM: S[b,n] = 2 * sum_d A[b,d]*C[n,d] - csum[n]
// 128x128 tile, BK=8, 256 threads, 8x8 per-thread microtile.
// Both operands are K-major (row-major with K contiguous) -> "NT" gemm.
// ---------------------------------------------------------------------------
__global__ void __launch_bounds__(256, 2)
gemm_kernel(const float* __restrict__ A, const float* __restrict__ Cb) {
    __shared__ float As[BK][LDS_STRIDE];
    __shared__ float Bs[BK][LDS_STRIDE];

    const int tid = threadIdx.x;
    const int m0  = blockIdx.y * BM;
    const int n0  = blockIdx.x * BN;
    const int tm  = tid >> 4;    // 0..15
    const int tn  = tid & 15;    // 0..15

    // Global load mapping: thread loads one float4 of A and one of C per k-step
    const int lr = tid >> 1;           // 0..127 : row within tile
    const int lk = (tid & 1) * 4;      // 0 or 4 : k offset within BK
    const float* Ap = A  + (size_t)(m0 + lr) * KDIM + lk;
    const bool bvalid = (n0 + lr) < NCLS;
    const float* Bp = Cb + (size_t)(bvalid ? (n0 + lr) : 0) * KDIM + lk;

    float acc[TM][TN];
    #pragma unroll
    for (int i = 0; i < TM; i++)
        #pragma unroll
        for (int j = 0; j < TN; j++) acc[i][j] = 0.f;

    for (int k0 = 0; k0 < KDIM; k0 += BK) {
        float4 a4 = *reinterpret_cast<const float4*>(Ap + k0);
        float4 b4 = bvalid ? *reinterpret_cast<const float4*>(Bp + k0)
                           : make_float4(0.f, 0.f, 0.f, 0.f);
        __syncthreads();
        As[lk + 0][lr] = a4.x; As[lk + 1][lr] = a4.y;
        As[lk + 2][lr] = a4.z; As[lk + 3][lr] = a4.w;
        Bs[lk + 0][lr] = b4.x; Bs[lk + 1][lr] = b4.y;
        Bs[lk + 2][lr] = b4.z; Bs[lk + 3][lr] = b4.w;
        __syncthreads();

        #pragma unroll
        for (int k = 0; k < BK; k++) {
            const float4* ap = reinterpret_cast<const float4*>(&As[k][tm * TM]);
            const float4* bp = reinterpret_cast<const float4*>(&Bs[k][tn * TN]);
            float4 a0 = ap[0], a1 = ap[1];
            float4 b0 = bp[0], b1 = bp[1];
            float a[TM] = {a0.x, a0.y, a0.z, a0.w, a1.x, a1.y, a1.z, a1.w};
            float b[TN] = {b0.x, b0.y, b0.z, b0.w, b1.x, b1.y, b1.z, b1.w};
            #pragma unroll
            for (int i = 0; i < TM; i++)
                #pragma unroll
                for (int j = 0; j < TN; j++)
                    acc[i][j] = fmaf(a[i], b[j], acc[i][j]);
        }
    }

    // Epilogue: S = 2*acc - csum[col]
    float cs[TN];
    #pragma unroll
    for (int j = 0; j < TN; j++) {
        int col = n0 + tn * TN + j;
        cs[j] = (col < NCLS) ? g_csum[col] : 0.f;
    }
    #pragma unroll
    for (int i = 0; i < TM; i++) {
        int row = m0 + tm * TM + i;
        float* out = g_S + (size_t)row * NCLS;
        #pragma unroll
        for (int j = 0; j < TN; j++) {
            int col = n0 + tn * TN + j;
            if (col < NCLS)
                out[col] = 2.f * acc[i][j] - cs[j];
        }
    }
}

// ---------------------------------------------------------------------------
// Per-row reduction: one warp per row.
//   g_row[b] = lse(S_b) - (EPS/N) * sum_n S_bn - (1-EPS) * S[b, label_b]
// ---------------------------------------------------------------------------
__global__ void rowreduce_kernel(const int* __restrict__ l32) {
    const int warp = (blockIdx.x * blockDim.x + threadIdx.x) >> 5;
    const int lane = threadIdx.x & 31;
    if (warp >= B_ROWS) return;

    const float* s = g_S + (size_t)warp * NCLS;

    float v[32];
    float mx = -3.402823466e38f;
    #pragma unroll
    for (int j = 0; j < 32; j++) {
        int n = lane + 32 * j;
        v[j] = (n < NCLS) ? s[n] : -3.402823466e38f;
        mx = fmaxf(mx, v[j]);
    }
    #pragma unroll
    for (int off = 16; off > 0; off >>= 1)
        mx = fmaxf(mx, __shfl_xor_sync(0xFFFFFFFFu, mx, off));

    float se = 0.f, ss = 0.f;
    #pragma unroll
    for (int j = 0; j < 32; j++) {
        int n = lane + 32 * j;
        if (n < NCLS) {
            se += __expf(v[j] - mx);
            ss += v[j];
        }
    }
    #pragma unroll
    for (int off = 16; off > 0; off >>= 1) {
        se += __shfl_xor_sync(0xFFFFFFFFu, se, off);
        ss += __shfl_xor_sync(0xFFFFFFFFu, ss, off);
    }

    if (lane == 0) {
        int lab = g_labmode ? l32[warp] : l32[2 * warp];  // int32 vs int64(lo word)
        float slab = s[lab];
        float lse  = mx + logf(se);
        g_row[warp] = lse - (EPS / (float)NCLS) * ss - (1.0f - EPS) * slab;
    }
}

// ---------------------------------------------------------------------------
// Deterministic final mean: single block, fixed reduction order.
// ---------------------------------------------------------------------------
__global__ void finalize_kernel(float* __restrict__ out) {
    __shared__ float warp_sums[8];
    float s = 0.f;
    for (int i = threadIdx.x; i < B_ROWS; i += 256)
        s += g_row[i];
    #pragma unroll
    for (int off = 16; off > 0; off >>= 1)
        s += __shfl_xor_sync(0xFFFFFFFFu, s, off);
    if ((threadIdx.x & 31) == 0) warp_sums[threadIdx.x >> 5] = s;
    __syncthreads();
    if (threadIdx.x == 0) {
        float t = 0.f;
        #pragma unroll
        for (int w = 0; w < 8; w++) t += warp_sums[w];
        out[0] = t / (float)B_ROWS;
    }
}

// ---------------------------------------------------------------------------
extern "C" void kernel_launch(void* const* d_in, const int* in_sizes, int n_in,
                              void* d_out, int out_size) {
    const float* A   = (const float*)d_in[0];   // inputs [16384, 1000]
    const int*   lab = (const int*)d_in[1];     // labels (int32 or int64 — detected)
    const float* Cb  = (const float*)d_in[2];   // code_book [1000, 1000]
    float* out = (float*)d_out;

    detect_kernel<<<1, 256>>>(lab);
    csum_kernel<<<(NCLS * 32 + 255) / 256, 256>>>(Cb);
    dim3 grid((NCLS + BN - 1) / BN, B_ROWS / BM);
    gemm_kernel<<<grid, 256>>>(A, Cb);
    rowreduce_kernel<<<(B_ROWS * 32 + 255) / 256, 256>>>(lab);
    finalize_kernel<<<1, 256>>>(out);
}

// round 3
// speedup vs baseline: 1.0017x; 1.0017x over previous
#include <cuda_runtime.h>
#include <math.h>

#define B_ROWS 16384
#define NCLS   1000
#define KDIM   1000
#define EPS    0.1f

#define BM 128
#define BN 128
#define BK 8
#define TM 8
#define TN 8
#define LDS_STRIDE 132   // 128 + 4 pad to kill store bank conflicts

// Scratch (allocation-free rule: __device__ globals)
__device__ float g_S[(size_t)B_ROWS * NCLS];   // logits S[b,n] = 2*dot - csum[n]
__device__ float g_csum[NCLS];
__device__ float g_row[B_ROWS];
__device__ int   g_labmode;                    // 1 = int32 labels, 0 = int64 labels

// ---------------------------------------------------------------------------
// Detect label dtype: if labels are int64 (little-endian), every odd int32
// word is the hi word of a value in [0,1000) -> all zero. If int32, the odd
// words are actual labels; 8192 of them all being zero has ~nil probability.
// Only scans the first 16384 int32s, which is in-bounds for either dtype.
// ---------------------------------------------------------------------------
__global__ void detect_kernel(const int* __restrict__ l32) {
    __shared__ int s_any;
    if (threadIdx.x == 0) s_any = 0;
    __syncthreads();
    int local = 0;
    for (int i = threadIdx.x; i < B_ROWS / 2; i += blockDim.x)
        local |= l32[2 * i + 1];
    if (local) atomicOr(&s_any, 1);
    __syncthreads();
    if (threadIdx.x == 0) g_labmode = (s_any != 0) ? 1 : 0;
}

// ---------------------------------------------------------------------------
// csum[n] = sum_d code_book[n, d]   (one warp per codebook row)
// ---------------------------------------------------------------------------
__global__ void csum_kernel(const float* __restrict__ Cb) {
    int warp = (blockIdx.x * blockDim.x + threadIdx.x) >> 5;
    int lane = threadIdx.x & 31;
    if (warp >= NCLS) return;
    const float* r = Cb + (size_t)warp * KDIM;
    float s = 0.f;
    for (int i = lane; i < KDIM; i += 32) s += r[i];
    #pragma unroll
    for (int off = 16; off > 0; off >>= 1)
        s += __shfl_xor_sync(0xFFFFFFFFu, s, off);
    if (lane == 0) g_csum[warp] = s;
}

// ---------------------------------------------------------------------------
// Tiled SGEMM: S[b,n] = 2 * sum_d A[b,d]*C[n,d] - csum[n]
// 128x128 tile, BK=8, 256 threads, 8x8 per-thread microtile.
// Both operands are K-major (row-major with K contiguous) -> "NT" gemm.
// ---------------------------------------------------------------------------
__global__ void __launch_bounds__(256, 2)
gemm_kernel(const float* __restrict__ A, const float* __restrict__ Cb) {
    __shared__ float As[BK][LDS_STRIDE];
    __shared__ float Bs[BK][LDS_STRIDE];

    const int tid = threadIdx.x;
    const int m0  = blockIdx.y * BM;
    const int n0  = blockIdx.x * BN;
    const int tm  = tid >> 4;    // 0..15
    const int tn  = tid & 15;    // 0..15

    // Global load mapping: thread loads one float4 of A and one of C per k-step
    const int lr = tid >> 1;           // 0..127 : row within tile
    const int lk = (tid & 1) * 4;      // 0 or 4 : k offset within BK
    const float* Ap = A  + (size_t)(m0 + lr) * KDIM + lk;
    const bool bvalid = (n0 + lr) < NCLS;
    const float* Bp = Cb + (size_t)(bvalid ? (n0 + lr) : 0) * KDIM + lk;

    float acc[TM][TN];
    #pragma unroll
    for (int i = 0; i < TM; i++)
        #pragma unroll
        for (int j = 0; j < TN; j++) acc[i][j] = 0.f;

    for (int k0 = 0; k0 < KDIM; k0 += BK) {
        float4 a4 = *reinterpret_cast<const float4*>(Ap + k0);
        float4 b4 = bvalid ? *reinterpret_cast<const float4*>(Bp + k0)
                           : make_float4(0.f, 0.f, 0.f, 0.f);
        __syncthreads();
        As[lk + 0][lr] = a4.x; As[lk + 1][lr] = a4.y;
        As[lk + 2][lr] = a4.z; As[lk + 3][lr] = a4.w;
        Bs[lk + 0][lr] = b4.x; Bs[lk + 1][lr] = b4.y;
        Bs[lk + 2][lr] = b4.z; Bs[lk + 3][lr] = b4.w;
        __syncthreads();

        #pragma unroll
        for (int k = 0; k < BK; k++) {
            const float4* ap = reinterpret_cast<const float4*>(&As[k][tm * TM]);
            const float4* bp = reinterpret_cast<const float4*>(&Bs[k][tn * TN]);
            float4 a0 = ap[0], a1 = ap[1];
            float4 b0 = bp[0], b1 = bp[1];
            float a[TM] = {a0.x, a0.y, a0.z, a0.w, a1.x, a1.y, a1.z, a1.w};
            float b[TN] = {b0.x, b0.y, b0.z, b0.w, b1.x, b1.y, b1.z, b1.w};
            #pragma unroll
            for (int i = 0; i < TM; i++)
                #pragma unroll
                for (int j = 0; j < TN; j++)
                    acc[i][j] = fmaf(a[i], b[j], acc[i][j]);
        }
    }

    // Epilogue: S = 2*acc - csum[col]
    float cs[TN];
    #pragma unroll
    for (int j = 0; j < TN; j++) {
        int col = n0 + tn * TN + j;
        cs[j] = (col < NCLS) ? g_csum[col] : 0.f;
    }
    #pragma unroll
    for (int i = 0; i < TM; i++) {
        int row = m0 + tm * TM + i;
        float* out = g_S + (size_t)row * NCLS;
        #pragma unroll
        for (int j = 0; j < TN; j++) {
            int col = n0 + tn * TN + j;
            if (col < NCLS)
                out[col] = 2.f * acc[i][j] - cs[j];
        }
    }
}

// ---------------------------------------------------------------------------
// Per-row reduction: one warp per row.
//   g_row[b] = lse(S_b) - (EPS/N) * sum_n S_bn - (1-EPS) * S[b, label_b]
// ---------------------------------------------------------------------------
__global__ void rowreduce_kernel(const int* __restrict__ l32) {
    const int warp = (blockIdx.x * blockDim.x + threadIdx.x) >> 5;
    const int lane = threadIdx.x & 31;
    if (warp >= B_ROWS) return;

    const float* s = g_S + (size_t)warp * NCLS;

    float v[32];
    float mx = -3.402823466e38f;
    #pragma unroll
    for (int j = 0; j < 32; j++) {
        int n = lane + 32 * j;
        v[j] = (n < NCLS) ? s[n] : -3.402823466e38f;
        mx = fmaxf(mx, v[j]);
    }
    #pragma unroll
    for (int off = 16; off > 0; off >>= 1)
        mx = fmaxf(mx, __shfl_xor_sync(0xFFFFFFFFu, mx, off));

    float se = 0.f, ss = 0.f;
    #pragma unroll
    for (int j = 0; j < 32; j++) {
        int n = lane + 32 * j;
        if (n < NCLS) {
            se += __expf(v[j] - mx);
            ss += v[j];
        }
    }
    #pragma unroll
    for (int off = 16; off > 0; off >>= 1) {
        se += __shfl_xor_sync(0xFFFFFFFFu, se, off);
        ss += __shfl_xor_sync(0xFFFFFFFFu, ss, off);
    }

    if (lane == 0) {
        int lab = g_labmode ? l32[warp] : l32[2 * warp];  // int32 vs int64(lo word)
        float slab = s[lab];
        float lse  = mx + logf(se);
        g_row[warp] = lse - (EPS / (float)NCLS) * ss - (1.0f - EPS) * slab;
    }
}

// ---------------------------------------------------------------------------
// Deterministic final mean: single block, fixed reduction order.
// ---------------------------------------------------------------------------
__global__ void finalize_kernel(float* __restrict__ out) {
    __shared__ float warp_sums[8];
    float s = 0.f;
    for (int i = threadIdx.x; i < B_ROWS; i += 256)
        s += g_row[i];
    #pragma unroll
    for (int off = 16; off > 0; off >>= 1)
        s += __shfl_xor_sync(0xFFFFFFFFu, s, off);
    if ((threadIdx.x & 31) == 0) warp_sums[threadIdx.x >> 5] = s;
    __syncthreads();
    if (threadIdx.x == 0) {
        float t = 0.f;
        #pragma unroll
        for (int w = 0; w < 8; w++) t += warp_sums[w];
        out[0] = t / (float)B_ROWS;
    }
}

// ---------------------------------------------------------------------------
extern "C" void kernel_launch(void* const* d_in, const int* in_sizes, int n_in,
                              void* d_out, int out_size) {
    const float* A   = (const float*)d_in[0];   // inputs [16384, 1000]
    const int*   lab = (const int*)d_in[1];     // labels (int32 or int64 — detected)
    const float* Cb  = (const float*)d_in[2];   // code_book [1000, 1000]
    float* out = (float*)d_out;

    detect_kernel<<<1, 256>>>(lab);
    csum_kernel<<<(NCLS * 32 + 255) / 256, 256>>>(Cb);
    dim3 grid((NCLS + BN - 1) / BN, B_ROWS / BM);
    gemm_kernel<<<grid, 256>>>(A, Cb);
    rowreduce_kernel<<<(B_ROWS * 32 + 255) / 256, 256>>>(lab);
    finalize_kernel<<<1, 256>>>(out);
}